// round 3
// baseline (speedup 1.0000x reference)
#include <cuda_runtime.h>
#include <math.h>

// ---------------- constants ----------------
#define BATCH   4
#define DIM     64
#define HIDDEN  170
#define C2      340           // 2*HIDDEN
#define HW      65536         // 256*256
#define WIDTH   256
#define PP      8
#define PF      5

typedef unsigned long long u64;

// ---------------- scratch (device globals; no allocation allowed) ----------------
__device__ float g_xin [(size_t)BATCH * C2 * HW];      // 356 MB
__device__ float g_feat[(size_t)BATCH * HIDDEN * HW];  // 178 MB (feat, then spatial in-place)
__device__ float g_part[BATCH * HIDDEN * 64];          // per-block partial sums for gap
__device__ float g_mod [BATCH];

// packed f32x2 FMA: d = a*b + d  (SASS FFMA2, 2 fp32 FMAs per instruction)
__device__ __forceinline__ void ffma2(u64& d, u64 a, u64 b) {
    asm("fma.rn.f32x2 %0, %1, %2, %0;" : "+l"(d) : "l"(a), "l"(b));
}
__device__ __forceinline__ u64 dupf(float v) {
    unsigned int u = __float_as_uint(v);
    return ((u64)u << 32) | (u64)u;
}

// ---------------- complex helpers ----------------
__device__ __forceinline__ float2 cmul(float2 a, float2 b) {
    return make_float2(a.x * b.x - a.y * b.y, a.x * b.y + a.y * b.x);
}
__device__ __forceinline__ float2 cadd(float2 a, float2 b) { return make_float2(a.x + b.x, a.y + b.y); }
__device__ __forceinline__ float2 csub(float2 a, float2 b) { return make_float2(a.x - b.x, a.y - b.y); }

template <int SIGN>
__device__ __forceinline__ void cfft8(float2 x[8]) {
    float2 e0 = x[0], e1 = x[2], e2 = x[4], e3 = x[6];
    float2 o0 = x[1], o1 = x[3], o2 = x[5], o3 = x[7];
    float2 t0 = cadd(e0, e2), t1 = csub(e0, e2), t2 = cadd(e1, e3), t3 = csub(e1, e3);
    float2 rt3 = (SIGN < 0) ? make_float2(t3.y, -t3.x) : make_float2(-t3.y, t3.x);
    float2 E0 = cadd(t0, t2), E2 = csub(t0, t2), E1 = cadd(t1, rt3), E3 = csub(t1, rt3);
    t0 = cadd(o0, o2); t1 = csub(o0, o2); t2 = cadd(o1, o3); t3 = csub(o1, o3);
    rt3 = (SIGN < 0) ? make_float2(t3.y, -t3.x) : make_float2(-t3.y, t3.x);
    float2 O0 = cadd(t0, t2), O2 = csub(t0, t2), O1 = cadd(t1, rt3), O3 = csub(t1, rt3);
    const float s = 0.70710678118654752f;
    const float2 w1 = make_float2(s, (SIGN < 0) ? -s : s);
    const float2 w2 = make_float2(0.f, (SIGN < 0) ? -1.f : 1.f);
    const float2 w3 = make_float2(-s, (SIGN < 0) ? -s : s);
    float2 a;
    a = O0;           x[0] = cadd(E0, a); x[4] = csub(E0, a);
    a = cmul(w1, O1); x[1] = cadd(E1, a); x[5] = csub(E1, a);
    a = cmul(w2, O2); x[2] = cadd(E2, a); x[6] = csub(E2, a);
    a = cmul(w3, O3); x[3] = cadd(E3, a); x[7] = csub(E3, a);
}

__device__ __forceinline__ void rfft8(float4 r0, float4 r1, float2 out[5]) {
    float e0 = r0.x, e1 = r0.z, e2 = r1.x, e3 = r1.z;
    float o0 = r0.y, o1 = r0.w, o2 = r1.y, o3 = r1.w;
    float ep = e0 + e2, em = e0 - e2, eq = e1 + e3, er = e1 - e3;
    float op = o0 + o2, om = o0 - o2, oq = o1 + o3, orr = o1 - o3;
    float E0 = ep + eq, E2 = ep - eq;
    float O0 = op + oq, O2 = op - oq;
    const float s = 0.70710678118654752f;
    float w1x = s * (om - orr), w1y = s * (-orr - om);
    float w3x = s * (orr - om), w3y = -s * (om + orr);
    out[0] = make_float2(E0 + O0, 0.f);
    out[1] = make_float2(em + w1x, -er + w1y);
    out[2] = make_float2(E2, -O2);
    out[3] = make_float2(em + w3x, er + w3y);
    out[4] = make_float2(E0 - O0, 0.f);
}

__device__ __forceinline__ float gelu_exact(float x) {
    return 0.5f * x * (1.f + erff(x * 0.70710678118654752f));
}

// ---------------- K1: x_in = w_in @ x  (340x64 @ 64x65536 per batch, FFMA2) ----------------
__global__ void __launch_bounds__(256) gemm1_kernel(const float* __restrict__ x,
                                                    const float* __restrict__ w_in) {
    __shared__ float Bs[64][128];   // x tile [c][pos]
    __shared__ u64   As2[64][64];   // w tile [c][o], value duplicated into both f32x2 lanes
    const int b = blockIdx.y;
    const int pos0 = blockIdx.x * 128;
    const int t = threadIdx.x;
    const int pg = t & 31;          // 32 position groups * 4
    const int og = t >> 5;          // 8 o groups * 8

    const float* xb = x + ((size_t)b * 64) * HW + pos0;
#pragma unroll
    for (int i = 0; i < 8; i++) {
        int idx = t + i * 256;
        int cc = idx >> 5, p4 = idx & 31;
        *(float4*)&Bs[cc][p4 * 4] = *(const float4*)(xb + (size_t)cc * HW + p4 * 4);
    }

    for (int ot = 0; ot < 6; ot++) {
        const int ob = ot * 64;
        __syncthreads();
#pragma unroll
        for (int i = 0; i < 16; i++) {
            int idx = t + i * 256;
            int oo = idx >> 6, cc = idx & 63;
            int o = ob + oo;
            As2[cc][oo] = dupf((o < C2) ? w_in[o * 64 + cc] : 0.f);
        }
        __syncthreads();

        u64 acc[16];
#pragma unroll
        for (int i = 0; i < 16; i++) acc[i] = 0ull;

#pragma unroll 8
        for (int cc = 0; cc < 64; cc++) {
            ulonglong2 bv = *(const ulonglong2*)&Bs[cc][pg * 4];
            const u64* ap = &As2[cc][og * 8];
#pragma unroll
            for (int i = 0; i < 8; i++) {
                u64 a = ap[i];
                ffma2(acc[2 * i],     a, bv.x);
                ffma2(acc[2 * i + 1], a, bv.y);
            }
        }
#pragma unroll
        for (int i = 0; i < 8; i++) {
            int o = ob + og * 8 + i;
            if (o < C2) {
                ulonglong2 r; r.x = acc[2 * i]; r.y = acc[2 * i + 1];
                *(ulonglong2*)&g_xin[((size_t)(b * C2 + o)) * HW + pos0 + pg * 4] = r;
            }
        }
    }
}

// ---------------- K2: depthwise 3x3 + gelu gate + gap partials ----------------
__device__ __forceinline__ float4 conv3x3(const float* __restrict__ base,
                                          const float* __restrict__ wt,
                                          int h, int w0) {
    float k0 = __ldg(wt + 0), k1 = __ldg(wt + 1), k2 = __ldg(wt + 2);
    float k3 = __ldg(wt + 3), k4 = __ldg(wt + 4), k5 = __ldg(wt + 5);
    float k6 = __ldg(wt + 6), k7 = __ldg(wt + 7), k8 = __ldg(wt + 8);
    float ax = 0.f, ay = 0.f, az = 0.f, aw = 0.f;
#pragma unroll
    for (int dy = 0; dy < 3; dy++) {
        int hy = h + dy - 1;
        if (hy < 0 || hy > 255) continue;
        const float* row = base + hy * WIDTH + w0;
        float4 m = *(const float4*)row;
        float lm = (w0 > 0)   ? __ldg(row - 1) : 0.f;
        float rm = (w0 < 252) ? __ldg(row + 4) : 0.f;
        float c0 = (dy == 0) ? k0 : (dy == 1) ? k3 : k6;
        float c1 = (dy == 0) ? k1 : (dy == 1) ? k4 : k7;
        float c2 = (dy == 0) ? k2 : (dy == 1) ? k5 : k8;
        ax += c0 * lm  + c1 * m.x + c2 * m.y;
        ay += c0 * m.x + c1 * m.y + c2 * m.z;
        az += c0 * m.y + c1 * m.z + c2 * m.w;
        aw += c0 * m.z + c1 * m.w + c2 * rm;
    }
    return make_float4(ax, ay, az, aw);
}

__global__ void __launch_bounds__(256) dwk(const float* __restrict__ w_dw) {
    const int bc = blockIdx.z;                 // b*170 + c
    const int b = bc / HIDDEN, c = bc % HIDDEN;
    const int tx = threadIdx.x & 15, ty = threadIdx.x >> 4;
    const int w0 = (blockIdx.x * 16 + tx) * 4;
    const int h  = blockIdx.y * 16 + ty;

    const float* base1 = g_xin + ((size_t)(b * C2 + c)) * HW;
    const float* base2 = g_xin + ((size_t)(b * C2 + c + HIDDEN)) * HW;
    float4 a1 = conv3x3(base1, w_dw + c * 9, h, w0);
    float4 a2 = conv3x3(base2, w_dw + (c + HIDDEN) * 9, h, w0);

    float4 f;
    f.x = gelu_exact(a1.x) * a2.x;
    f.y = gelu_exact(a1.y) * a2.y;
    f.z = gelu_exact(a1.z) * a2.z;
    f.w = gelu_exact(a1.w) * a2.w;
    *(float4*)&g_feat[((size_t)bc) * HW + h * WIDTH + w0] = f;

    float s = f.x + f.y + f.z + f.w;
    __shared__ float red[256];
    red[threadIdx.x] = s;
    __syncthreads();
#pragma unroll
    for (int off = 128; off > 0; off >>= 1) {
        if (threadIdx.x < off) red[threadIdx.x] += red[threadIdx.x + off];
        __syncthreads();
    }
    if (threadIdx.x == 0)
        g_part[bc * 64 + blockIdx.y * 4 + blockIdx.x] = red[0];
}

// ---------------- K3: gap reduce + modulation scalar (one kernel, grid=BATCH) ----------------
__global__ void __launch_bounds__(256) modk(const float* __restrict__ w_mod1,
                                            const float* __restrict__ w_mod2) {
    const int b = blockIdx.x;
    const int t = threadIdx.x;
    __shared__ float gap_s[HIDDEN];
    __shared__ float relu_s[16];

    for (int c = t; c < HIDDEN; c += 256) {
        const float* p = g_part + (size_t)(b * HIDDEN + c) * 64;
        float s = 0.f;
#pragma unroll
        for (int j = 0; j < 64; j++) s += p[j];
        gap_s[c] = s * (1.f / 65536.f);
    }
    __syncthreads();

    const int wid = t >> 5, lane = t & 31;
    for (int j = wid; j < 10; j += 8) {
        float s = 0.f;
        for (int c = lane; c < HIDDEN; c += 32)
            s += gap_s[c] * w_mod1[j * HIDDEN + c];
#pragma unroll
        for (int off = 16; off > 0; off >>= 1) s += __shfl_xor_sync(0xffffffff, s, off);
        if (lane == 0) relu_s[j] = fmaxf(s, 0.f);
    }
    __syncthreads();
    if (t == 0) {
        float m = 0.f;
#pragma unroll
        for (int j = 0; j < 10; j++) m += relu_s[j] * w_mod2[j];
        g_mod[b] = 1.f / (1.f + expf(-m));
    }
}

// ---------------- K4: per-patch rfft2 * S -> irfft2 (in place on g_feat) ----------------
__global__ void __launch_bounds__(256) fftk(const float* __restrict__ Wr,
                                            const float* __restrict__ Wi,
                                            const float* __restrict__ csc) {
    const int bc = blockIdx.y;
    const int b = bc / HIDDEN, c = bc % HIDDEN;
    __shared__ float2 S[PP * PF];
    const int t = threadIdx.x;
    if (t < PP * PF) {
        int ky = t / PF, kx = t % PF;
        float mask = expf(-(float)(ky * ky + kx * kx) * (1.f / 18.f));
        float boost = 1.f + mask * (csc[c] * (0.5f + g_mod[b]));
        float sc = boost * (1.f / 64.f);
        S[t] = make_float2(Wr[c * 40 + t] * sc, Wi[c * 40 + t] * sc);
    }
    __syncthreads();

    const int p = blockIdx.x * 256 + t;
    float* base = g_feat + (((size_t)bc) << 16) + (p >> 5) * (PP * WIDTH) + (p & 31) * PP;

    float2 F[5][8];
#pragma unroll
    for (int y = 0; y < 8; y++) {
        float4 r0 = *(const float4*)(base + y * WIDTH);
        float4 r1 = *(const float4*)(base + y * WIDTH + 4);
        float2 o5[5];
        rfft8(r0, r1, o5);
#pragma unroll
        for (int k = 0; k < 5; k++) F[k][y] = o5[k];
    }
#pragma unroll
    for (int k = 0; k < 5; k++) cfft8<-1>(F[k]);
#pragma unroll
    for (int k = 0; k < 5; k++)
#pragma unroll
        for (int ky = 0; ky < 8; ky++)
            F[k][ky] = cmul(F[k][ky], S[ky * PF + k]);
#pragma unroll
    for (int k = 0; k < 5; k++) cfft8<1>(F[k]);
#pragma unroll
    for (int y = 0; y < 8; y++) {
        float2 z[8];
        z[0] = make_float2(F[0][y].x, 0.f);
        z[1] = F[1][y]; z[2] = F[2][y]; z[3] = F[3][y];
        z[4] = make_float2(F[4][y].x, 0.f);
        z[5] = make_float2(F[3][y].x, -F[3][y].y);
        z[6] = make_float2(F[2][y].x, -F[2][y].y);
        z[7] = make_float2(F[1][y].x, -F[1][y].y);
        cfft8<1>(z);
        *(float4*)(base + y * WIDTH)     = make_float4(z[0].x, z[1].x, z[2].x, z[3].x);
        *(float4*)(base + y * WIDTH + 4) = make_float4(z[4].x, z[5].x, z[6].x, z[7].x);
    }
}

// ---------------- K5: out = w_out @ spatial  (64x170 @ 170x65536 per batch, FFMA2) ----------------
__global__ void __launch_bounds__(256) gemm2_kernel(const float* __restrict__ w_out,
                                                    float* __restrict__ out) {
    __shared__ float Bs[34][128];
    __shared__ u64   As2[34][64];   // [c][o], duplicated lanes
    const int b = blockIdx.y;
    const int pos0 = blockIdx.x * 128;
    const int t = threadIdx.x;
    const int pg = t & 31, og = t >> 5;

    u64 acc[16];
#pragma unroll
    for (int i = 0; i < 16; i++) acc[i] = 0ull;

    for (int kc = 0; kc < 5; kc++) {
        const int c0 = kc * 34;
        __syncthreads();
        for (int idx = t; idx < 34 * 32; idx += 256) {
            int cc = idx >> 5, p4 = idx & 31;
            *(float4*)&Bs[cc][p4 * 4] =
                *(const float4*)&g_feat[((size_t)(b * HIDDEN + c0 + cc)) * HW + pos0 + p4 * 4];
        }
        for (int idx = t; idx < 34 * 64; idx += 256) {
            int cc = idx % 34, oo = idx / 34;
            As2[cc][oo] = dupf(w_out[oo * HIDDEN + c0 + cc]);
        }
        __syncthreads();
#pragma unroll 2
        for (int cc = 0; cc < 34; cc++) {
            ulonglong2 bv = *(const ulonglong2*)&Bs[cc][pg * 4];
            const u64* ap = &As2[cc][og * 8];
#pragma unroll
            for (int i = 0; i < 8; i++) {
                u64 a = ap[i];
                ffma2(acc[2 * i],     a, bv.x);
                ffma2(acc[2 * i + 1], a, bv.y);
            }
        }
    }
#pragma unroll
    for (int i = 0; i < 8; i++) {
        int o = og * 8 + i;
        ulonglong2 r; r.x = acc[2 * i]; r.y = acc[2 * i + 1];
        *(ulonglong2*)&out[((size_t)(b * 64 + o)) * HW + pos0 + pg * 4] = r;
    }
}

// ---------------- launch ----------------
extern "C" void kernel_launch(void* const* d_in, const int* in_sizes, int n_in,
                              void* d_out, int out_size) {
    const float* x     = (const float*)d_in[0];
    const float* w_in  = (const float*)d_in[1];
    const float* w_dw  = (const float*)d_in[2];
    const float* w_out = (const float*)d_in[3];
    const float* Wr    = (const float*)d_in[4];
    const float* Wi    = (const float*)d_in[5];
    const float* csc   = (const float*)d_in[6];
    const float* wm1   = (const float*)d_in[7];
    const float* wm2   = (const float*)d_in[8];
    float* out = (float*)d_out;

    gemm1_kernel<<<dim3(512, BATCH), 256>>>(x, w_in);
    dwk<<<dim3(4, 16, BATCH * HIDDEN), 256>>>(w_dw);
    modk<<<BATCH, 256>>>(wm1, wm2);
    fftk<<<dim3(4, BATCH * HIDDEN), 256>>>(Wr, Wi, csc);
    gemm2_kernel<<<dim3(512, BATCH), 256>>>(w_out, out);
}

// round 5
// speedup vs baseline: 1.5471x; 1.5471x over previous
#include <cuda_runtime.h>
#include <cuda_bf16.h>
#include <math.h>
#include <cstdint>

// ---------------- constants ----------------
#define BATCH   4
#define DIM     64
#define HIDDEN  170
#define C2      340           // 2*HIDDEN
#define HW      65536         // 256*256
#define WIDTH   256
#define PP      8
#define PF      5

// ---------------- scratch (device globals; no allocation allowed) ----------------
__device__ float g_xin [(size_t)BATCH * C2 * HW];      // 356 MB
__device__ float g_feat[(size_t)BATCH * HIDDEN * HW];  // 178 MB (feat, then spatial in-place)
__device__ float g_part[BATCH * HIDDEN * 64];
__device__ float g_mod [BATCH];
__device__ __nv_bfloat16 g_w1s[2][384][64];            // w_in  split: [hi/lo][o pad][k]
__device__ __nv_bfloat16 g_w2s[2][64][176];            // w_out split: [hi/lo][o][k pad]

// ---------------- helpers ----------------
// pack two f32 into bf16x2 word: low half = a, high half = b
__device__ __forceinline__ uint32_t pack2(float a, float b) {
    uint32_t r;
    asm("cvt.rn.bf16x2.f32 %0, %1, %2;" : "=r"(r) : "f"(b), "f"(a));
    return r;
}
// bf16-split of 4 floats -> hi word pair + lo word pair
__device__ __forceinline__ void split4(float v0, float v1, float v2, float v3,
                                       uint2& hi, uint2& lo) {
    uint32_t h01 = pack2(v0, v1), h23 = pack2(v2, v3);
    float f0 = __uint_as_float(h01 << 16),  f1 = __uint_as_float(h01 & 0xffff0000u);
    float f2 = __uint_as_float(h23 << 16),  f3 = __uint_as_float(h23 & 0xffff0000u);
    hi = make_uint2(h01, h23);
    lo = make_uint2(pack2(v0 - f0, v1 - f1), pack2(v2 - f2, v3 - f3));
}

__device__ __forceinline__ void mma16816(float d[4], const uint32_t a[4], const uint32_t b[2]) {
    asm volatile(
        "mma.sync.aligned.m16n8k16.row.col.f32.bf16.bf16.f32 "
        "{%0,%1,%2,%3}, {%4,%5,%6,%7}, {%8,%9}, {%0,%1,%2,%3};"
        : "+f"(d[0]), "+f"(d[1]), "+f"(d[2]), "+f"(d[3])
        : "r"(a[0]), "r"(a[1]), "r"(a[2]), "r"(a[3]), "r"(b[0]), "r"(b[1]));
}

// smem tile layout: [ktile][row][16 bf16 = 32B], bit-4 XOR swizzle on (row>>2)&1
__device__ __forceinline__ uint32_t tile_addr(int ktile, int row, int kin2bytes, int kstride) {
    return (uint32_t)(ktile * kstride + ((row * 32 + kin2bytes) ^ (((row >> 2) & 1) << 4)));
}

// ================= K0: weight split prep =================
__global__ void __launch_bounds__(256) wsplit(const float* __restrict__ w_in,
                                              const float* __restrict__ w_out) {
    int i = blockIdx.x * 256 + threadIdx.x;
    if (i < 384 * 64) {
        int o = i >> 6, k = i & 63;
        float v = (o < C2) ? w_in[o * 64 + k] : 0.f;
        __nv_bfloat16 h = __float2bfloat16(v);
        g_w1s[0][o][k] = h;
        g_w1s[1][o][k] = __float2bfloat16(v - __bfloat162float(h));
    }
    if (i < 64 * 176) {
        int o = i / 176, k = i - o * 176;
        float v = (k < HIDDEN) ? w_out[o * HIDDEN + k] : 0.f;
        __nv_bfloat16 h = __float2bfloat16(v);
        g_w2s[0][o][k] = h;
        g_w2s[1][o][k] = __float2bfloat16(v - __bfloat162float(h));
    }
}

// ================= K1: x_in = w_in @ x via mma.sync =================
// block: pos=128, o=384 (3 chunks of 128), K=64 -> 8 ktiles (4 hi + 4 lo)
// smem: A 32KB | B 32KB | stg 32KB
__global__ void __launch_bounds__(256) gemm1_tc(const float* __restrict__ x) {
    extern __shared__ char smem[];
    char* As = smem;
    char* Bs = smem + 32768;
    float* stg = (float*)(smem + 65536);
    const int t = threadIdx.x, lane = t & 31, w = t >> 5;
    const int g = lane >> 2, q = lane & 3;
    const int b = blockIdx.y, pos0 = blockIdx.x * 128;
    const int wy = w & 3, wx = w >> 2;     // warp grid: 4 pos x 2 o

    // stage x tile [64c][128pos]
    const float* xb = x + ((size_t)b * 64) * HW + pos0;
#pragma unroll
    for (int i = 0; i < 8; i++) {
        int idx = t + i * 256, cc = idx >> 5, p4 = idx & 31;
        *(float4*)&stg[cc * 128 + p4 * 4] = *(const float4*)(xb + (size_t)cc * HW + p4 * 4);
    }
    __syncthreads();
    // convert A -> bf16 hi (ktiles 0..3) / lo (4..7)
#pragma unroll
    for (int i = 0; i < 8; i++) {
        int idx = t + i * 256;
        int pos = idx & 127, k = (idx >> 7) * 4;
        float v0 = stg[(k + 0) * 128 + pos], v1 = stg[(k + 1) * 128 + pos];
        float v2 = stg[(k + 2) * 128 + pos], v3 = stg[(k + 3) * 128 + pos];
        uint2 hi, lo; split4(v0, v1, v2, v3, hi, lo);
        uint32_t ah = tile_addr(k >> 4, pos, (k & 15) * 2, 4096);
        *(uint2*)(As + ah) = hi;
        *(uint2*)(As + ah + 4 * 4096) = lo;
    }

    for (int oc = 0; oc < 3; oc++) {
        // fill B chunk: 128 o x (4 hi + 4 lo) ktiles
#pragma unroll
        for (int pl = 0; pl < 2; pl++)
#pragma unroll
            for (int i = 0; i < 8; i++) {
                int idx = t + i * 256;
                int o = idx >> 4, k = (idx & 15) * 4;
                uint2 v = *(const uint2*)&g_w1s[pl][oc * 128 + o][k];
                *(uint2*)(Bs + tile_addr(pl * 4 + (k >> 4), o, (k & 15) * 2, 4096)) = v;
            }
        __syncthreads();

        float acc[2][8][4];
#pragma unroll
        for (int m = 0; m < 2; m++)
#pragma unroll
            for (int n = 0; n < 8; n++)
#pragma unroll
                for (int j = 0; j < 4; j++) acc[m][n][j] = 0.f;

#pragma unroll
        for (int s = 0; s < 12; s++) {
            int at = (s < 8) ? s : s - 8;    // hi,lo,hi
            int bt = (s < 4) ? s : s - 4;    // hi,hi,lo
            const char* ab = As + at * 4096;
            uint32_t af[2][4];
#pragma unroll
            for (int mt = 0; mt < 2; mt++) {
                int p0 = wy * 32 + mt * 16 + g, p1 = p0 + 8;
                uint32_t a0 = (uint32_t)((p0 * 32 + q * 4) ^ (((p0 >> 2) & 1) << 4));
                uint32_t a1 = (uint32_t)((p1 * 32 + q * 4) ^ (((p1 >> 2) & 1) << 4));
                af[mt][0] = *(const uint32_t*)(ab + a0);
                af[mt][1] = *(const uint32_t*)(ab + a1);
                af[mt][2] = *(const uint32_t*)(ab + (a0 ^ 16));
                af[mt][3] = *(const uint32_t*)(ab + (a1 ^ 16));
            }
            const char* bb = Bs + bt * 4096;
#pragma unroll
            for (int nt = 0; nt < 8; nt++) {
                int o = wx * 64 + nt * 8 + g;
                uint32_t b0 = (uint32_t)((o * 32 + q * 4) ^ (((o >> 2) & 1) << 4));
                uint32_t bf[2];
                bf[0] = *(const uint32_t*)(bb + b0);
                bf[1] = *(const uint32_t*)(bb + (b0 ^ 16));
                mma16816(acc[0][nt], af[0], bf);
                mma16816(acc[1][nt], af[1], bf);
            }
        }

        // store chunk
#pragma unroll
        for (int mt = 0; mt < 2; mt++)
#pragma unroll
            for (int nt = 0; nt < 8; nt++) {
                int o = oc * 128 + wx * 64 + nt * 8 + q * 2;
                if (o < C2) {
                    int pos = pos0 + wy * 32 + mt * 16 + g;
                    float* p = g_xin + ((size_t)(b * C2 + o)) * HW + pos;
                    p[0]      = acc[mt][nt][0];
                    p[HW]     = acc[mt][nt][1];
                    p[8]      = acc[mt][nt][2];
                    p[HW + 8] = acc[mt][nt][3];
                }
            }
        __syncthreads();
    }
}

// ================= K5: out = w_out @ spatial via mma.sync =================
// block: pos=128, o=64, K=170 -> 11 hi + 11 lo ktiles, 33 mma steps
// smem: A 88KB | B 44KB | stg 32KB
__global__ void __launch_bounds__(256) gemm2_tc(float* __restrict__ out) {
    extern __shared__ char smem[];
    char* As = smem;                       // 22 * 4096
    char* Bs = smem + 90112;               // 22 * 2048
    float* stg = (float*)(smem + 135168);
    const int t = threadIdx.x, lane = t & 31, w = t >> 5;
    const int g = lane >> 2, q = lane & 3;
    const int b = blockIdx.y, pos0 = blockIdx.x * 128;
    const int wy = w & 3, wx = w >> 2;

    // zero A (pad columns 170..175 must be zero)
    for (int i = t; i < 90112 / 16; i += 256) ((uint4*)As)[i] = make_uint4(0, 0, 0, 0);

    // fill B: 2 planes x 64 o x 176 k
    for (int i = t; i < 2 * 64 * 44; i += 256) {
        int pl = i / (64 * 44), r = i - pl * (64 * 44);
        int o = r / 44, k = (r - o * 44) * 4;
        uint2 v = *(const uint2*)&g_w2s[pl][o][k];
        *(uint2*)(Bs + tile_addr(pl * 11 + (k >> 4), o, (k & 15) * 2, 2048)) = v;
    }

    // fill A in 3 passes of up to 64 channels
    for (int pass = 0; pass < 3; pass++) {
        const int c0 = pass * 64;
        const int cnt = (pass == 2) ? 42 : 64;
        __syncthreads();
#pragma unroll
        for (int i = 0; i < 8; i++) {
            int idx = t + i * 256, cc = idx >> 5, p4 = idx & 31;
            if (cc < cnt)
                *(float4*)&stg[cc * 128 + p4 * 4] =
                    *(const float4*)&g_feat[((size_t)(b * HIDDEN + c0 + cc)) * HW + pos0 + p4 * 4];
        }
        __syncthreads();
#pragma unroll
        for (int i = 0; i < 8; i++) {
            int idx = t + i * 256;
            int pos = idx & 127, kk = (idx >> 7) * 4;
            if (kk >= cnt) continue;
            float v0 = (kk + 0 < cnt) ? stg[(kk + 0) * 128 + pos] : 0.f;
            float v1 = (kk + 1 < cnt) ? stg[(kk + 1) * 128 + pos] : 0.f;
            float v2 = (kk + 2 < cnt) ? stg[(kk + 2) * 128 + pos] : 0.f;
            float v3 = (kk + 3 < cnt) ? stg[(kk + 3) * 128 + pos] : 0.f;
            uint2 hi, lo; split4(v0, v1, v2, v3, hi, lo);
            int k = c0 + kk;
            uint32_t ah = tile_addr(k >> 4, pos, (k & 15) * 2, 4096);
            *(uint2*)(As + ah) = hi;
            *(uint2*)(As + ah + 11 * 4096) = lo;
        }
    }
    __syncthreads();

    float acc[2][4][4];
#pragma unroll
    for (int m = 0; m < 2; m++)
#pragma unroll
        for (int n = 0; n < 4; n++)
#pragma unroll
            for (int j = 0; j < 4; j++) acc[m][n][j] = 0.f;

#pragma unroll 11
    for (int s = 0; s < 33; s++) {
        int at = (s < 22) ? s : s - 22;    // hi, lo, hi
        int bt = (s < 11) ? s : s - 11;    // hi, hi, lo
        const char* ab = As + at * 4096;
        uint32_t af[2][4];
#pragma unroll
        for (int mt = 0; mt < 2; mt++) {
            int p0 = wy * 32 + mt * 16 + g, p1 = p0 + 8;
            uint32_t a0 = (uint32_t)((p0 * 32 + q * 4) ^ (((p0 >> 2) & 1) << 4));
            uint32_t a1 = (uint32_t)((p1 * 32 + q * 4) ^ (((p1 >> 2) & 1) << 4));
            af[mt][0] = *(const uint32_t*)(ab + a0);
            af[mt][1] = *(const uint32_t*)(ab + a1);
            af[mt][2] = *(const uint32_t*)(ab + (a0 ^ 16));
            af[mt][3] = *(const uint32_t*)(ab + (a1 ^ 16));
        }
        const char* bb = Bs + bt * 2048;
#pragma unroll
        for (int nt = 0; nt < 4; nt++) {
            int o = wx * 32 + nt * 8 + g;
            uint32_t b0 = (uint32_t)((o * 32 + q * 4) ^ (((o >> 2) & 1) << 4));
            uint32_t bf[2];
            bf[0] = *(const uint32_t*)(bb + b0);
            bf[1] = *(const uint32_t*)(bb + (b0 ^ 16));
            mma16816(acc[0][nt], af[0], bf);
            mma16816(acc[1][nt], af[1], bf);
        }
    }

#pragma unroll
    for (int mt = 0; mt < 2; mt++)
#pragma unroll
        for (int nt = 0; nt < 4; nt++) {
            int o = wx * 32 + nt * 8 + q * 2;
            int pos = pos0 + wy * 32 + mt * 16 + g;
            float* p = out + ((size_t)(b * 64 + o)) * HW + pos;
            p[0]      = acc[mt][nt][0];
            p[HW]     = acc[mt][nt][1];
            p[8]      = acc[mt][nt][2];
            p[HW + 8] = acc[mt][nt][3];
        }
}

// ================= K2: depthwise 3x3 + gelu gate + gap partials =================
__device__ __forceinline__ float4 conv3x3(const float* __restrict__ base,
                                          const float* __restrict__ wt,
                                          int h, int w0) {
    float k0 = __ldg(wt + 0), k1 = __ldg(wt + 1), k2 = __ldg(wt + 2);
    float k3 = __ldg(wt + 3), k4 = __ldg(wt + 4), k5 = __ldg(wt + 5);
    float k6 = __ldg(wt + 6), k7 = __ldg(wt + 7), k8 = __ldg(wt + 8);
    float ax = 0.f, ay = 0.f, az = 0.f, aw = 0.f;
#pragma unroll
    for (int dy = 0; dy < 3; dy++) {
        int hy = h + dy - 1;
        if (hy < 0 || hy > 255) continue;
        const float* row = base + hy * WIDTH + w0;
        float4 m = *(const float4*)row;
        float lm = (w0 > 0)   ? __ldg(row - 1) : 0.f;
        float rm = (w0 < 252) ? __ldg(row + 4) : 0.f;
        float c0 = (dy == 0) ? k0 : (dy == 1) ? k3 : k6;
        float c1 = (dy == 0) ? k1 : (dy == 1) ? k4 : k7;
        float c2 = (dy == 0) ? k2 : (dy == 1) ? k5 : k8;
        ax += c0 * lm  + c1 * m.x + c2 * m.y;
        ay += c0 * m.x + c1 * m.y + c2 * m.z;
        az += c0 * m.y + c1 * m.z + c2 * m.w;
        aw += c0 * m.z + c1 * m.w + c2 * rm;
    }
    return make_float4(ax, ay, az, aw);
}
__device__ __forceinline__ float gelu_exact(float x) {
    return 0.5f * x * (1.f + erff(x * 0.70710678118654752f));
}

__global__ void __launch_bounds__(256) dwk(const float* __restrict__ w_dw) {
    const int bc = blockIdx.z;
    const int b = bc / HIDDEN, c = bc % HIDDEN;
    const int tx = threadIdx.x & 15, ty = threadIdx.x >> 4;
    const int w0 = (blockIdx.x * 16 + tx) * 4;
    const int h  = blockIdx.y * 16 + ty;

    const float* base1 = g_xin + ((size_t)(b * C2 + c)) * HW;
    const float* base2 = g_xin + ((size_t)(b * C2 + c + HIDDEN)) * HW;
    float4 a1 = conv3x3(base1, w_dw + c * 9, h, w0);
    float4 a2 = conv3x3(base2, w_dw + (c + HIDDEN) * 9, h, w0);

    float4 f;
    f.x = gelu_exact(a1.x) * a2.x;
    f.y = gelu_exact(a1.y) * a2.y;
    f.z = gelu_exact(a1.z) * a2.z;
    f.w = gelu_exact(a1.w) * a2.w;
    *(float4*)&g_feat[((size_t)bc) * HW + h * WIDTH + w0] = f;

    float s = f.x + f.y + f.z + f.w;
    __shared__ float red[256];
    red[threadIdx.x] = s;
    __syncthreads();
#pragma unroll
    for (int off = 128; off > 0; off >>= 1) {
        if (threadIdx.x < off) red[threadIdx.x] += red[threadIdx.x + off];
        __syncthreads();
    }
    if (threadIdx.x == 0)
        g_part[bc * 64 + blockIdx.y * 4 + blockIdx.x] = red[0];
}

// ================= K3: gap reduce + modulation =================
__global__ void __launch_bounds__(256) modk(const float* __restrict__ w_mod1,
                                            const float* __restrict__ w_mod2) {
    const int b = blockIdx.x;
    const int t = threadIdx.x;
    __shared__ float gap_s[HIDDEN];
    __shared__ float relu_s[16];

    for (int c = t; c < HIDDEN; c += 256) {
        const float* p = g_part + (size_t)(b * HIDDEN + c) * 64;
        float s = 0.f;
#pragma unroll
        for (int j = 0; j < 64; j++) s += p[j];
        gap_s[c] = s * (1.f / 65536.f);
    }
    __syncthreads();

    const int wid = t >> 5, lane = t & 31;
    for (int j = wid; j < 10; j += 8) {
        float s = 0.f;
        for (int c = lane; c < HIDDEN; c += 32)
            s += gap_s[c] * w_mod1[j * HIDDEN + c];
#pragma unroll
        for (int off = 16; off > 0; off >>= 1) s += __shfl_xor_sync(0xffffffff, s, off);
        if (lane == 0) relu_s[j] = fmaxf(s, 0.f);
    }
    __syncthreads();
    if (t == 0) {
        float m = 0.f;
#pragma unroll
        for (int j = 0; j < 10; j++) m += relu_s[j] * w_mod2[j];
        g_mod[b] = 1.f / (1.f + expf(-m));
    }
}

// ================= K4: per-patch rfft2 * S -> irfft2 =================
__device__ __forceinline__ float2 cmul(float2 a, float2 b) {
    return make_float2(a.x * b.x - a.y * b.y, a.x * b.y + a.y * b.x);
}
__device__ __forceinline__ float2 cadd(float2 a, float2 b) { return make_float2(a.x + b.x, a.y + b.y); }
__device__ __forceinline__ float2 csub(float2 a, float2 b) { return make_float2(a.x - b.x, a.y - b.y); }

template <int SIGN>
__device__ __forceinline__ void cfft8(float2 x[8]) {
    float2 e0 = x[0], e1 = x[2], e2 = x[4], e3 = x[6];
    float2 o0 = x[1], o1 = x[3], o2 = x[5], o3 = x[7];
    float2 t0 = cadd(e0, e2), t1 = csub(e0, e2), t2 = cadd(e1, e3), t3 = csub(e1, e3);
    float2 rt3 = (SIGN < 0) ? make_float2(t3.y, -t3.x) : make_float2(-t3.y, t3.x);
    float2 E0 = cadd(t0, t2), E2 = csub(t0, t2), E1 = cadd(t1, rt3), E3 = csub(t1, rt3);
    t0 = cadd(o0, o2); t1 = csub(o0, o2); t2 = cadd(o1, o3); t3 = csub(o1, o3);
    rt3 = (SIGN < 0) ? make_float2(t3.y, -t3.x) : make_float2(-t3.y, t3.x);
    float2 O0 = cadd(t0, t2), O2 = csub(t0, t2), O1 = cadd(t1, rt3), O3 = csub(t1, rt3);
    const float s = 0.70710678118654752f;
    const float2 w1 = make_float2(s, (SIGN < 0) ? -s : s);
    const float2 w2 = make_float2(0.f, (SIGN < 0) ? -1.f : 1.f);
    const float2 w3 = make_float2(-s, (SIGN < 0) ? -s : s);
    float2 a;
    a = O0;           x[0] = cadd(E0, a); x[4] = csub(E0, a);
    a = cmul(w1, O1); x[1] = cadd(E1, a); x[5] = csub(E1, a);
    a = cmul(w2, O2); x[2] = cadd(E2, a); x[6] = csub(E2, a);
    a = cmul(w3, O3); x[3] = cadd(E3, a); x[7] = csub(E3, a);
}

__device__ __forceinline__ void rfft8(float4 r0, float4 r1, float2 out[5]) {
    float e0 = r0.x, e1 = r0.z, e2 = r1.x, e3 = r1.z;
    float o0 = r0.y, o1 = r0.w, o2 = r1.y, o3 = r1.w;
    float ep = e0 + e2, em = e0 - e2, eq = e1 + e3, er = e1 - e3;
    float op = o0 + o2, om = o0 - o2, oq = o1 + o3, orr = o1 - o3;
    float E0 = ep + eq, E2 = ep - eq;
    float O0 = op + oq, O2 = op - oq;
    const float s = 0.70710678118654752f;
    float w1x = s * (om - orr), w1y = s * (-orr - om);
    float w3x = s * (orr - om), w3y = -s * (om + orr);
    out[0] = make_float2(E0 + O0, 0.f);
    out[1] = make_float2(em + w1x, -er + w1y);
    out[2] = make_float2(E2, -O2);
    out[3] = make_float2(em + w3x, er + w3y);
    out[4] = make_float2(E0 - O0, 0.f);
}

__global__ void __launch_bounds__(256) fftk(const float* __restrict__ Wr,
                                            const float* __restrict__ Wi,
                                            const float* __restrict__ csc) {
    const int bc = blockIdx.y;
    const int b = bc / HIDDEN, c = bc % HIDDEN;
    __shared__ float2 S[PP * PF];
    const int t = threadIdx.x;
    if (t < PP * PF) {
        int ky = t / PF, kx = t % PF;
        float mask = expf(-(float)(ky * ky + kx * kx) * (1.f / 18.f));
        float boost = 1.f + mask * (csc[c] * (0.5f + g_mod[b]));
        float sc = boost * (1.f / 64.f);
        S[t] = make_float2(Wr[c * 40 + t] * sc, Wi[c * 40 + t] * sc);
    }
    __syncthreads();

    const int p = blockIdx.x * 256 + t;
    float* base = g_feat + (((size_t)bc) << 16) + (p >> 5) * (PP * WIDTH) + (p & 31) * PP;

    float2 F[5][8];
#pragma unroll
    for (int y = 0; y < 8; y++) {
        float4 r0 = *(const float4*)(base + y * WIDTH);
        float4 r1 = *(const float4*)(base + y * WIDTH + 4);
        float2 o5[5];
        rfft8(r0, r1, o5);
#pragma unroll
        for (int k = 0; k < 5; k++) F[k][y] = o5[k];
    }
#pragma unroll
    for (int k = 0; k < 5; k++) cfft8<-1>(F[k]);
#pragma unroll
    for (int k = 0; k < 5; k++)
#pragma unroll
        for (int ky = 0; ky < 8; ky++)
            F[k][ky] = cmul(F[k][ky], S[ky * PF + k]);
#pragma unroll
    for (int k = 0; k < 5; k++) cfft8<1>(F[k]);
#pragma unroll
    for (int y = 0; y < 8; y++) {
        float2 z[8];
        z[0] = make_float2(F[0][y].x, 0.f);
        z[1] = F[1][y]; z[2] = F[2][y]; z[3] = F[3][y];
        z[4] = make_float2(F[4][y].x, 0.f);
        z[5] = make_float2(F[3][y].x, -F[3][y].y);
        z[6] = make_float2(F[2][y].x, -F[2][y].y);
        z[7] = make_float2(F[1][y].x, -F[1][y].y);
        cfft8<1>(z);
        *(float4*)(base + y * WIDTH)     = make_float4(z[0].x, z[1].x, z[2].x, z[3].x);
        *(float4*)(base + y * WIDTH + 4) = make_float4(z[4].x, z[5].x, z[6].x, z[7].x);
    }
}

// ================= launch =================
extern "C" void kernel_launch(void* const* d_in, const int* in_sizes, int n_in,
                              void* d_out, int out_size) {
    const float* x     = (const float*)d_in[0];
    const float* w_in  = (const float*)d_in[1];
    const float* w_dw  = (const float*)d_in[2];
    const float* w_out = (const float*)d_in[3];
    const float* Wr    = (const float*)d_in[4];
    const float* Wi    = (const float*)d_in[5];
    const float* csc   = (const float*)d_in[6];
    const float* wm1   = (const float*)d_in[7];
    const float* wm2   = (const float*)d_in[8];
    float* out = (float*)d_out;

    cudaFuncSetAttribute(gemm1_tc, cudaFuncAttributeMaxDynamicSharedMemorySize, 98304);
    cudaFuncSetAttribute(gemm2_tc, cudaFuncAttributeMaxDynamicSharedMemorySize, 167936);

    wsplit<<<96, 256>>>(w_in, w_out);
    gemm1_tc<<<dim3(512, BATCH), 256, 98304>>>(x);
    dwk<<<dim3(4, 16, BATCH * HIDDEN), 256>>>(w_dw);
    modk<<<BATCH, 256>>>(wm1, wm2);
    fftk<<<dim3(4, BATCH * HIDDEN), 256>>>(Wr, Wi, csc);
    gemm2_tc<<<dim3(512, BATCH), 256, 167936>>>(out);
}

// round 6
// speedup vs baseline: 1.8673x; 1.2070x over previous
#include <cuda_runtime.h>
#include <cuda_bf16.h>
#include <math.h>
#include <cstdint>

// ---------------- constants ----------------
#define BATCH   4
#define DIM     64
#define HIDDEN  170
#define C2      340           // 2*HIDDEN
#define HW      65536         // 256*256
#define WIDTH   256
#define PP      8
#define PF      5
#define PARTS   32            // gap partials per (b,c)

// ---------------- scratch (device globals; no allocation allowed) ----------------
__device__ float g_xin [(size_t)BATCH * C2 * HW];      // 356 MB
__device__ float g_feat[(size_t)BATCH * HIDDEN * HW];  // 178 MB (feat, then spatial in-place)
__device__ float g_part[BATCH * HIDDEN * PARTS];
__device__ float g_mod [BATCH];
__device__ __nv_bfloat16 g_w1s[2][384][64];            // w_in  split: [hi/lo][o pad][k]
__device__ __nv_bfloat16 g_w2s[2][64][176];            // w_out split: [hi/lo][o][k pad]

// ---------------- helpers ----------------
__device__ __forceinline__ uint32_t pack2(float a, float b) {
    uint32_t r;
    asm("cvt.rn.bf16x2.f32 %0, %1, %2;" : "=r"(r) : "f"(b), "f"(a));
    return r;
}
__device__ __forceinline__ void split4(float v0, float v1, float v2, float v3,
                                       uint2& hi, uint2& lo) {
    uint32_t h01 = pack2(v0, v1), h23 = pack2(v2, v3);
    float f0 = __uint_as_float(h01 << 16),  f1 = __uint_as_float(h01 & 0xffff0000u);
    float f2 = __uint_as_float(h23 << 16),  f3 = __uint_as_float(h23 & 0xffff0000u);
    hi = make_uint2(h01, h23);
    lo = make_uint2(pack2(v0 - f0, v1 - f1), pack2(v2 - f2, v3 - f3));
}

__device__ __forceinline__ void mma16816(float d[4], const uint32_t a[4], const uint32_t b[2]) {
    asm volatile(
        "mma.sync.aligned.m16n8k16.row.col.f32.bf16.bf16.f32 "
        "{%0,%1,%2,%3}, {%4,%5,%6,%7}, {%8,%9}, {%0,%1,%2,%3};"
        : "+f"(d[0]), "+f"(d[1]), "+f"(d[2]), "+f"(d[3])
        : "r"(a[0]), "r"(a[1]), "r"(a[2]), "r"(a[3]), "r"(b[0]), "r"(b[1]));
}

// smem tile layout: [ktile][row][16 bf16 = 32B], bit-4 XOR swizzle on (row>>2)&1
__device__ __forceinline__ uint32_t tile_addr(int ktile, int row, int kin2bytes, int kstride) {
    return (uint32_t)(ktile * kstride + ((row * 32 + kin2bytes) ^ (((row >> 2) & 1) << 4)));
}

// ================= K0: weight split prep =================
__global__ void __launch_bounds__(256) wsplit(const float* __restrict__ w_in,
                                              const float* __restrict__ w_out) {
    int i = blockIdx.x * 256 + threadIdx.x;
    if (i < 384 * 64) {
        int o = i >> 6, k = i & 63;
        float v = (o < C2) ? w_in[o * 64 + k] : 0.f;
        __nv_bfloat16 h = __float2bfloat16(v);
        g_w1s[0][o][k] = h;
        g_w1s[1][o][k] = __float2bfloat16(v - __bfloat162float(h));
    }
    if (i < 64 * 176) {
        int o = i / 176, k = i - o * 176;
        float v = (k < HIDDEN) ? w_out[o * HIDDEN + k] : 0.f;
        __nv_bfloat16 h = __float2bfloat16(v);
        g_w2s[0][o][k] = h;
        g_w2s[1][o][k] = __float2bfloat16(v - __bfloat162float(h));
    }
}

// profiler-alignment no-op (puts gemm1 at launch index 3)
__global__ void noop() {}

// ================= K1: x_in = w_in @ x via mma.sync =================
// block: pos=128, o=384 (3 chunks of 128), K=64 -> 8 ktiles (4 hi + 4 lo)
// smem: A 32KB | B 32KB | stg 32KB
__global__ void __launch_bounds__(256) gemm1_tc(const float* __restrict__ x) {
    extern __shared__ char smem[];
    char* As = smem;
    char* Bs = smem + 32768;
    float* stg = (float*)(smem + 65536);
    const int t = threadIdx.x, lane = t & 31, w = t >> 5;
    const int g = lane >> 2, q = lane & 3;
    const int b = blockIdx.y, pos0 = blockIdx.x * 128;
    const int wy = w & 3, wx = w >> 2;     // warp grid: 4 pos x 2 o

    // stage x tile [64c][128pos]
    const float* xb = x + ((size_t)b * 64) * HW + pos0;
#pragma unroll
    for (int i = 0; i < 8; i++) {
        int idx = t + i * 256, cc = idx >> 5, p4 = idx & 31;
        *(float4*)&stg[cc * 128 + p4 * 4] = *(const float4*)(xb + (size_t)cc * HW + p4 * 4);
    }
    __syncthreads();
    // convert A -> bf16 hi (ktiles 0..3) / lo (4..7)
#pragma unroll
    for (int i = 0; i < 8; i++) {
        int idx = t + i * 256;
        int pos = idx & 127, k = (idx >> 7) * 4;
        float v0 = stg[(k + 0) * 128 + pos], v1 = stg[(k + 1) * 128 + pos];
        float v2 = stg[(k + 2) * 128 + pos], v3 = stg[(k + 3) * 128 + pos];
        uint2 hi, lo; split4(v0, v1, v2, v3, hi, lo);
        uint32_t ah = tile_addr(k >> 4, pos, (k & 15) * 2, 4096);
        *(uint2*)(As + ah) = hi;
        *(uint2*)(As + ah + 4 * 4096) = lo;
    }

    for (int oc = 0; oc < 3; oc++) {
        // fill B chunk: 128 o x (4 hi + 4 lo) ktiles
#pragma unroll
        for (int pl = 0; pl < 2; pl++)
#pragma unroll
            for (int i = 0; i < 8; i++) {
                int idx = t + i * 256;
                int o = idx >> 4, k = (idx & 15) * 4;
                uint2 v = *(const uint2*)&g_w1s[pl][oc * 128 + o][k];
                *(uint2*)(Bs + tile_addr(pl * 4 + (k >> 4), o, (k & 15) * 2, 4096)) = v;
            }
        __syncthreads();

        float acc[2][8][4];
#pragma unroll
        for (int m = 0; m < 2; m++)
#pragma unroll
            for (int n = 0; n < 8; n++)
#pragma unroll
                for (int j = 0; j < 4; j++) acc[m][n][j] = 0.f;

#pragma unroll
        for (int s = 0; s < 12; s++) {
            int at = (s < 8) ? s : s - 8;    // hi,lo,hi
            int bt = (s < 4) ? s : s - 4;    // hi,hi,lo
            const char* ab = As + at * 4096;
            uint32_t af[2][4];
#pragma unroll
            for (int mt = 0; mt < 2; mt++) {
                int p0 = wy * 32 + mt * 16 + g, p1 = p0 + 8;
                uint32_t a0 = (uint32_t)((p0 * 32 + q * 4) ^ (((p0 >> 2) & 1) << 4));
                uint32_t a1 = (uint32_t)((p1 * 32 + q * 4) ^ (((p1 >> 2) & 1) << 4));
                af[mt][0] = *(const uint32_t*)(ab + a0);
                af[mt][1] = *(const uint32_t*)(ab + a1);
                af[mt][2] = *(const uint32_t*)(ab + (a0 ^ 16));
                af[mt][3] = *(const uint32_t*)(ab + (a1 ^ 16));
            }
            const char* bb = Bs + bt * 4096;
#pragma unroll
            for (int nt = 0; nt < 8; nt++) {
                int o = wx * 64 + nt * 8 + g;
                uint32_t b0 = (uint32_t)((o * 32 + q * 4) ^ (((o >> 2) & 1) << 4));
                uint32_t bf[2];
                bf[0] = *(const uint32_t*)(bb + b0);
                bf[1] = *(const uint32_t*)(bb + (b0 ^ 16));
                mma16816(acc[0][nt], af[0], bf);
                mma16816(acc[1][nt], af[1], bf);
            }
        }

        // store chunk
#pragma unroll
        for (int mt = 0; mt < 2; mt++)
#pragma unroll
            for (int nt = 0; nt < 8; nt++) {
                int o = oc * 128 + wx * 64 + nt * 8 + q * 2;
                if (o < C2) {
                    int pos = pos0 + wy * 32 + mt * 16 + g;
                    float* p = g_xin + ((size_t)(b * C2 + o)) * HW + pos;
                    p[0]      = acc[mt][nt][0];
                    p[HW]     = acc[mt][nt][1];
                    p[8]      = acc[mt][nt][2];
                    p[HW + 8] = acc[mt][nt][3];
                }
            }
        __syncthreads();
    }
}

// ================= K5: out = w_out @ spatial via mma.sync (chunked K) =================
// smem: B 44KB | A chunk 32KB | stg 32KB = 108KB -> 2 blocks/SM
__global__ void __launch_bounds__(256) gemm2_tc(float* __restrict__ out) {
    extern __shared__ char smem[];
    char* Bs = smem;                       // 22 * 2048 = 45056
    char* As = smem + 45056;               // 8 * 4096  = 32768
    float* stg = (float*)(smem + 45056 + 32768);
    const int t = threadIdx.x, lane = t & 31, w = t >> 5;
    const int g = lane >> 2, q = lane & 3;
    const int b = blockIdx.y, pos0 = blockIdx.x * 128;
    const int wy = w & 3, wx = w >> 2;

    // fill B: 2 planes x 64 o x 176 k (once)
    for (int i = t; i < 2 * 64 * 44; i += 256) {
        int pl = i / (64 * 44), r = i - pl * (64 * 44);
        int o = r / 44, k = (r - o * 44) * 4;
        uint2 v = *(const uint2*)&g_w2s[pl][o][k];
        *(uint2*)(Bs + tile_addr(pl * 11 + (k >> 4), o, (k & 15) * 2, 2048)) = v;
    }

    float acc[2][4][4];
#pragma unroll
    for (int m = 0; m < 2; m++)
#pragma unroll
        for (int n = 0; n < 4; n++)
#pragma unroll
            for (int j = 0; j < 4; j++) acc[m][n][j] = 0.f;

    for (int chunk = 0; chunk < 3; chunk++) {
        const int c0 = chunk * 64;
        const int nk = (chunk == 2) ? 3 : 4;      // A/B ktiles this chunk
        __syncthreads();                           // B ready (1st iter) / As free
        // stage 64 channels (zero-padded past HIDDEN)
#pragma unroll
        for (int i = 0; i < 8; i++) {
            int idx = t + i * 256, cc = idx >> 5, p4 = idx & 31;
            int c = c0 + cc;
            float4 v = make_float4(0.f, 0.f, 0.f, 0.f);
            if (c < HIDDEN)
                v = *(const float4*)&g_feat[((size_t)(b * HIDDEN + c)) * HW + pos0 + p4 * 4];
            *(float4*)&stg[cc * 128 + p4 * 4] = v;
        }
        __syncthreads();
        // convert chunk -> A ktiles 0..3 (hi) / 4..7 (lo)
#pragma unroll
        for (int i = 0; i < 8; i++) {
            int idx = t + i * 256;
            int pos = idx & 127, kk = (idx >> 7) * 4;
            float v0 = stg[(kk + 0) * 128 + pos], v1 = stg[(kk + 1) * 128 + pos];
            float v2 = stg[(kk + 2) * 128 + pos], v3 = stg[(kk + 3) * 128 + pos];
            uint2 hi, lo; split4(v0, v1, v2, v3, hi, lo);
            uint32_t ah = tile_addr(kk >> 4, pos, (kk & 15) * 2, 4096);
            *(uint2*)(As + ah) = hi;
            *(uint2*)(As + ah + 4 * 4096) = lo;
        }
        __syncthreads();

#pragma unroll
        for (int j = 0; j < 4; j++) {
            if (j >= nk) break;
            const char* abh = As + j * 4096;
            const char* abl = As + (4 + j) * 4096;
            uint32_t ah[2][4], al[2][4];
#pragma unroll
            for (int mt = 0; mt < 2; mt++) {
                int p0 = wy * 32 + mt * 16 + g, p1 = p0 + 8;
                uint32_t a0 = (uint32_t)((p0 * 32 + q * 4) ^ (((p0 >> 2) & 1) << 4));
                uint32_t a1 = (uint32_t)((p1 * 32 + q * 4) ^ (((p1 >> 2) & 1) << 4));
                ah[mt][0] = *(const uint32_t*)(abh + a0);
                ah[mt][1] = *(const uint32_t*)(abh + a1);
                ah[mt][2] = *(const uint32_t*)(abh + (a0 ^ 16));
                ah[mt][3] = *(const uint32_t*)(abh + (a1 ^ 16));
                al[mt][0] = *(const uint32_t*)(abl + a0);
                al[mt][1] = *(const uint32_t*)(abl + a1);
                al[mt][2] = *(const uint32_t*)(abl + (a0 ^ 16));
                al[mt][3] = *(const uint32_t*)(abl + (a1 ^ 16));
            }
            const char* bbh = Bs + (4 * chunk + j) * 2048;
            const char* bbl = Bs + (11 + 4 * chunk + j) * 2048;
#pragma unroll
            for (int nt = 0; nt < 4; nt++) {
                int o = wx * 32 + nt * 8 + g;
                uint32_t b0 = (uint32_t)((o * 32 + q * 4) ^ (((o >> 2) & 1) << 4));
                uint32_t bh[2], bl[2];
                bh[0] = *(const uint32_t*)(bbh + b0);
                bh[1] = *(const uint32_t*)(bbh + (b0 ^ 16));
                bl[0] = *(const uint32_t*)(bbl + b0);
                bl[1] = *(const uint32_t*)(bbl + (b0 ^ 16));
                mma16816(acc[0][nt], ah[0], bh);
                mma16816(acc[1][nt], ah[1], bh);
                mma16816(acc[0][nt], al[0], bh);
                mma16816(acc[1][nt], al[1], bh);
                mma16816(acc[0][nt], ah[0], bl);
                mma16816(acc[1][nt], ah[1], bl);
            }
        }
    }

#pragma unroll
    for (int mt = 0; mt < 2; mt++)
#pragma unroll
        for (int nt = 0; nt < 4; nt++) {
            int o = wx * 32 + nt * 8 + q * 2;
            int pos = pos0 + wy * 32 + mt * 16 + g;
            float* p = out + ((size_t)(b * 64 + o)) * HW + pos;
            p[0]      = acc[mt][nt][0];
            p[HW]     = acc[mt][nt][1];
            p[8]      = acc[mt][nt][2];
            p[HW + 8] = acc[mt][nt][3];
        }
}

// ================= K2: depthwise 3x3 + gelu gate + gap partials =================
__device__ __forceinline__ void conv8(const float* __restrict__ base,
                                      const float* __restrict__ wt,
                                      int h, int w0, float* a) {
    float k0 = __ldg(wt + 0), k1 = __ldg(wt + 1), k2 = __ldg(wt + 2);
    float k3 = __ldg(wt + 3), k4 = __ldg(wt + 4), k5 = __ldg(wt + 5);
    float k6 = __ldg(wt + 6), k7 = __ldg(wt + 7), k8 = __ldg(wt + 8);
#pragma unroll
    for (int j = 0; j < 8; j++) a[j] = 0.f;
#pragma unroll
    for (int dy = 0; dy < 3; dy++) {
        int hy = h + dy - 1;
        if (hy < 0 || hy > 255) continue;
        const float* row = base + hy * WIDTH + w0;
        float4 m0 = *(const float4*)row;
        float4 m1 = *(const float4*)(row + 4);
        float v[10];
        v[0] = (w0 > 0)   ? __ldg(row - 1) : 0.f;
        v[1] = m0.x; v[2] = m0.y; v[3] = m0.z; v[4] = m0.w;
        v[5] = m1.x; v[6] = m1.y; v[7] = m1.z; v[8] = m1.w;
        v[9] = (w0 < 248) ? __ldg(row + 8) : 0.f;
        float c0 = (dy == 0) ? k0 : (dy == 1) ? k3 : k6;
        float c1 = (dy == 0) ? k1 : (dy == 1) ? k4 : k7;
        float c2 = (dy == 0) ? k2 : (dy == 1) ? k5 : k8;
#pragma unroll
        for (int j = 0; j < 8; j++)
            a[j] += c0 * v[j] + c1 * v[j + 1] + c2 * v[j + 2];
    }
}
__device__ __forceinline__ float gelu_exact(float x) {
    return 0.5f * x * (1.f + erff(x * 0.70710678118654752f));
}

__global__ void __launch_bounds__(256) dwk(const float* __restrict__ w_dw) {
    const int bc = blockIdx.z;
    const int b = bc / HIDDEN, c = bc % HIDDEN;
    const int tx = threadIdx.x & 15, ty = threadIdx.x >> 4;
    const int w0 = (blockIdx.x * 16 + tx) * 8;   // 0..248
    const int h  = blockIdx.y * 16 + ty;

    const float* base1 = g_xin + ((size_t)(b * C2 + c)) * HW;
    const float* base2 = g_xin + ((size_t)(b * C2 + c + HIDDEN)) * HW;
    float a1[8], a2[8];
    conv8(base1, w_dw + c * 9, h, w0, a1);
    conv8(base2, w_dw + (c + HIDDEN) * 9, h, w0, a2);

    float f[8];
    float s = 0.f;
#pragma unroll
    for (int j = 0; j < 8; j++) {
        f[j] = gelu_exact(a1[j]) * a2[j];
        s += f[j];
    }
    float* op = g_feat + ((size_t)bc) * HW + h * WIDTH + w0;
    *(float4*)op       = make_float4(f[0], f[1], f[2], f[3]);
    *(float4*)(op + 4) = make_float4(f[4], f[5], f[6], f[7]);

    __shared__ float red[256];
    red[threadIdx.x] = s;
    __syncthreads();
#pragma unroll
    for (int off = 128; off > 0; off >>= 1) {
        if (threadIdx.x < off) red[threadIdx.x] += red[threadIdx.x + off];
        __syncthreads();
    }
    if (threadIdx.x == 0)
        g_part[bc * PARTS + blockIdx.y * 2 + blockIdx.x] = red[0];
}

// ================= K3: gap reduce + modulation =================
__global__ void __launch_bounds__(256) modk(const float* __restrict__ w_mod1,
                                            const float* __restrict__ w_mod2) {
    const int b = blockIdx.x;
    const int t = threadIdx.x;
    __shared__ float gap_s[HIDDEN];
    __shared__ float relu_s[16];

    for (int c = t; c < HIDDEN; c += 256) {
        const float* p = g_part + (size_t)(b * HIDDEN + c) * PARTS;
        float s = 0.f;
#pragma unroll
        for (int j = 0; j < PARTS; j++) s += p[j];
        gap_s[c] = s * (1.f / 65536.f);
    }
    __syncthreads();

    const int wid = t >> 5, lane = t & 31;
    for (int j = wid; j < 10; j += 8) {
        float s = 0.f;
        for (int c = lane; c < HIDDEN; c += 32)
            s += gap_s[c] * w_mod1[j * HIDDEN + c];
#pragma unroll
        for (int off = 16; off > 0; off >>= 1) s += __shfl_xor_sync(0xffffffff, s, off);
        if (lane == 0) relu_s[j] = fmaxf(s, 0.f);
    }
    __syncthreads();
    if (t == 0) {
        float m = 0.f;
#pragma unroll
        for (int j = 0; j < 10; j++) m += relu_s[j] * w_mod2[j];
        g_mod[b] = 1.f / (1.f + expf(-m));
    }
}

// ================= K4: per-patch rfft2 * S -> irfft2 =================
__device__ __forceinline__ float2 cmul(float2 a, float2 b) {
    return make_float2(a.x * b.x - a.y * b.y, a.x * b.y + a.y * b.x);
}
__device__ __forceinline__ float2 cadd(float2 a, float2 b) { return make_float2(a.x + b.x, a.y + b.y); }
__device__ __forceinline__ float2 csub(float2 a, float2 b) { return make_float2(a.x - b.x, a.y - b.y); }

template <int SIGN>
__device__ __forceinline__ void cfft8(float2 x[8]) {
    float2 e0 = x[0], e1 = x[2], e2 = x[4], e3 = x[6];
    float2 o0 = x[1], o1 = x[3], o2 = x[5], o3 = x[7];
    float2 t0 = cadd(e0, e2), t1 = csub(e0, e2), t2 = cadd(e1, e3), t3 = csub(e1, e3);
    float2 rt3 = (SIGN < 0) ? make_float2(t3.y, -t3.x) : make_float2(-t3.y, t3.x);
    float2 E0 = cadd(t0, t2), E2 = csub(t0, t2), E1 = cadd(t1, rt3), E3 = csub(t1, rt3);
    t0 = cadd(o0, o2); t1 = csub(o0, o2); t2 = cadd(o1, o3); t3 = csub(o1, o3);
    rt3 = (SIGN < 0) ? make_float2(t3.y, -t3.x) : make_float2(-t3.y, t3.x);
    float2 O0 = cadd(t0, t2), O2 = csub(t0, t2), O1 = cadd(t1, rt3), O3 = csub(t1, rt3);
    const float s = 0.70710678118654752f;
    const float2 w1 = make_float2(s, (SIGN < 0) ? -s : s);
    const float2 w2 = make_float2(0.f, (SIGN < 0) ? -1.f : 1.f);
    const float2 w3 = make_float2(-s, (SIGN < 0) ? -s : s);
    float2 a;
    a = O0;           x[0] = cadd(E0, a); x[4] = csub(E0, a);
    a = cmul(w1, O1); x[1] = cadd(E1, a); x[5] = csub(E1, a);
    a = cmul(w2, O2); x[2] = cadd(E2, a); x[6] = csub(E2, a);
    a = cmul(w3, O3); x[3] = cadd(E3, a); x[7] = csub(E3, a);
}

__device__ __forceinline__ void rfft8(float4 r0, float4 r1, float2 out[5]) {
    float e0 = r0.x, e1 = r0.z, e2 = r1.x, e3 = r1.z;
    float o0 = r0.y, o1 = r0.w, o2 = r1.y, o3 = r1.w;
    float ep = e0 + e2, em = e0 - e2, eq = e1 + e3, er = e1 - e3;
    float op = o0 + o2, om = o0 - o2, oq = o1 + o3, orr = o1 - o3;
    float E0 = ep + eq, E2 = ep - eq;
    float O0 = op + oq, O2 = op - oq;
    const float s = 0.70710678118654752f;
    float w1x = s * (om - orr), w1y = s * (-orr - om);
    float w3x = s * (orr - om), w3y = -s * (om + orr);
    out[0] = make_float2(E0 + O0, 0.f);
    out[1] = make_float2(em + w1x, -er + w1y);
    out[2] = make_float2(E2, -O2);
    out[3] = make_float2(em + w3x, er + w3y);
    out[4] = make_float2(E0 - O0, 0.f);
}

__global__ void __launch_bounds__(256) fftk(const float* __restrict__ Wr,
                                            const float* __restrict__ Wi,
                                            const float* __restrict__ csc) {
    const int bc = blockIdx.y;
    const int b = bc / HIDDEN, c = bc % HIDDEN;
    __shared__ float2 S[PP * PF];
    const int t = threadIdx.x;
    if (t < PP * PF) {
        int ky = t / PF, kx = t % PF;
        float mask = expf(-(float)(ky * ky + kx * kx) * (1.f / 18.f));
        float boost = 1.f + mask * (csc[c] * (0.5f + g_mod[b]));
        float sc = boost * (1.f / 64.f);
        S[t] = make_float2(Wr[c * 40 + t] * sc, Wi[c * 40 + t] * sc);
    }
    __syncthreads();

    const int p = blockIdx.x * 256 + t;
    float* base = g_feat + (((size_t)bc) << 16) + (p >> 5) * (PP * WIDTH) + (p & 31) * PP;

    float2 F[5][8];
#pragma unroll
    for (int y = 0; y < 8; y++) {
        float4 r0 = *(const float4*)(base + y * WIDTH);
        float4 r1 = *(const float4*)(base + y * WIDTH + 4);
        float2 o5[5];
        rfft8(r0, r1, o5);
#pragma unroll
        for (int k = 0; k < 5; k++) F[k][y] = o5[k];
    }
#pragma unroll
    for (int k = 0; k < 5; k++) cfft8<-1>(F[k]);
#pragma unroll
    for (int k = 0; k < 5; k++)
#pragma unroll
        for (int ky = 0; ky < 8; ky++)
            F[k][ky] = cmul(F[k][ky], S[ky * PF + k]);
#pragma unroll
    for (int k = 0; k < 5; k++) cfft8<1>(F[k]);
#pragma unroll
    for (int y = 0; y < 8; y++) {
        float2 z[8];
        z[0] = make_float2(F[0][y].x, 0.f);
        z[1] = F[1][y]; z[2] = F[2][y]; z[3] = F[3][y];
        z[4] = make_float2(F[4][y].x, 0.f);
        z[5] = make_float2(F[3][y].x, -F[3][y].y);
        z[6] = make_float2(F[2][y].x, -F[2][y].y);
        z[7] = make_float2(F[1][y].x, -F[1][y].y);
        cfft8<1>(z);
        *(float4*)(base + y * WIDTH)     = make_float4(z[0].x, z[1].x, z[2].x, z[3].x);
        *(float4*)(base + y * WIDTH + 4) = make_float4(z[4].x, z[5].x, z[6].x, z[7].x);
    }
}

// ================= launch =================
extern "C" void kernel_launch(void* const* d_in, const int* in_sizes, int n_in,
                              void* d_out, int out_size) {
    const float* x     = (const float*)d_in[0];
    const float* w_in  = (const float*)d_in[1];
    const float* w_dw  = (const float*)d_in[2];
    const float* w_out = (const float*)d_in[3];
    const float* Wr    = (const float*)d_in[4];
    const float* Wi    = (const float*)d_in[5];
    const float* csc   = (const float*)d_in[6];
    const float* wm1   = (const float*)d_in[7];
    const float* wm2   = (const float*)d_in[8];
    float* out = (float*)d_out;

    cudaFuncSetAttribute(gemm1_tc, cudaFuncAttributeMaxDynamicSharedMemorySize, 98304);
    cudaFuncSetAttribute(gemm2_tc, cudaFuncAttributeMaxDynamicSharedMemorySize, 110592);

    wsplit<<<96, 256>>>(w_in, w_out);
    noop<<<1, 32>>>();
    noop<<<1, 32>>>();
    gemm1_tc<<<dim3(512, BATCH), 256, 98304>>>(x);          // launch index 3 -> ncu window
    dwk<<<dim3(2, 16, BATCH * HIDDEN), 256>>>(w_dw);
    modk<<<BATCH, 256>>>(wm1, wm2);
    fftk<<<dim3(4, BATCH * HIDDEN), 256>>>(Wr, Wi, csc);
    gemm2_tc<<<dim3(512, BATCH), 256, 110592>>>(out);
}